// round 16
// baseline (speedup 1.0000x reference)
#include <cuda_runtime.h>
#include <cuda_bf16.h>
#include <cuda_fp16.h>

#define N_NODES 100000
#define N_EDGES 1600000
#define NFEAT   128
#define NHID    16
#define NCLS    40
#define NSCAN_BLOCKS 196
#define GEMM_BLOCKS ((N_NODES + 255) / 256)          // 391 (256 rows per block)
#define EDGE_BLOCKS ((N_EDGES / 4 + 255) / 256)      // 1563
#define TOTAL_BLOCKS (GEMM_BLOCKS + EDGE_BLOCKS)     // 1954

// -------- scratch (device globals; zero-initialized at module load) --------
__device__ float  g_ps[N_NODES * 16];   // x @ w_self1  (fp32)
__device__ __half g_pn[N_NODES * 16];   // x @ w_neigh1 (fp16, gathered per edge)
__device__ float  g_h [N_NODES * 16];   // layer-1 out fp32
__device__ __half g_hb[N_NODES * 16];   // layer-1 out fp16 (gathered per edge)
__device__ int    g_deg[N_NODES];       // INVARIANT: zero at entry/exit
__device__ int    g_rowptr[N_NODES + 1];
__device__ int    g_rank[N_EDGES];
__device__ int    g_eidx[N_EDGES];
__device__ unsigned long long g_scanstate[NSCAN_BLOCKS];

// ===================== fused FFMA2 GEMM1 + degree count ======================
// gemm blocks: 256 rows x 32 cols, 256 threads, 4 rows x 8 cols per thread.
// K staged in 8 chunks of 16 -> xs 20KB, total smem 36KB -> 3 CTAs/SM (regs).
#define XS_STRIDE 20   // 16 floats + pad 4; rows hit distinct bank quads

__device__ __forceinline__ void ffma2(unsigned long long& acc,
                                      unsigned long long a,
                                      unsigned long long b) {
    asm("fma.rn.f32x2 %0, %1, %2, %0;" : "+l"(acc) : "l"(a), "l"(b));
}

__global__ void __launch_bounds__(256) k_gemm_count(const float* __restrict__ x,
                                                    const float* __restrict__ wn1,
                                                    const float* __restrict__ ws1,
                                                    const int* __restrict__ dst) {
    __shared__ __align__(16) float xs[256 * XS_STRIDE];   // 20 KB
    __shared__ __align__(16) float wt2[4096];             // 16 KB
    int tid = threadIdx.x;

    if (blockIdx.x >= GEMM_BLOCKS) {
        // ---- count branch ----
        int cb = blockIdx.x - GEMM_BLOCKS;
        if (cb == 0 && tid < NSCAN_BLOCKS)
            *(volatile unsigned long long*)&g_scanstate[tid] = 0ULL;
        int e = cb * 256 + tid;
        if (e * 4 < N_EDGES) {
            int4 d = ((const int4*)dst)[e];
            int4 r;
            r.x = atomicAdd(&g_deg[d.x], 1);
            r.y = atomicAdd(&g_deg[d.y], 1);
            r.z = atomicAdd(&g_deg[d.z], 1);
            r.w = atomicAdd(&g_deg[d.w], 1);
            ((int4*)g_rank)[e] = r;
        }
        return;
    }

    // ---- gemm branch: 256 rows x 32 cols, f32x2 FFMA, K chunks of 16 ----
    int row0 = blockIdx.x * 256;

    // pack weights: wt2[k4g*128 + c*16 + cg*4 + j] = W[k4g*4+j][cg*8+c]
    for (int i = tid; i < 4096; i += 256) {
        int j   = i & 3;
        int cg  = (i >> 2) & 3;
        int c   = (i >> 4) & 7;
        int k4g = i >> 7;
        int col = cg * 8 + c;
        int k   = k4g * 4 + j;
        wt2[i] = (col < 16) ? ws1[k * 16 + col] : wn1[k * 16 + (col - 16)];
    }

    int cg = tid & 3;        // col group (0..3), 8 cols each
    int rg = tid >> 2;       // row group (0..63), rows rg + q*64

    unsigned long long acc[4][8];
#pragma unroll
    for (int q = 0; q < 4; q++)
#pragma unroll
        for (int c = 0; c < 8; c++) acc[q][c] = 0ULL;

#pragma unroll
    for (int chunk = 0; chunk < 8; chunk++) {
        __syncthreads();
        // stage 256 rows x 16 floats, coalesced (4 float4 per thread)
#pragma unroll
        for (int l = 0; l < 4; l++) {
            int f = l * 256 + tid;
            int row = f >> 2, slot = f & 3;
            int gr = row0 + row;
            if (gr >= N_NODES) gr = N_NODES - 1;   // clamp; stores guarded
            *(float4*)&xs[row * XS_STRIDE + slot * 4] =
                *(const float4*)&x[gr * 128 + chunk * 16 + slot * 4];
        }
        __syncthreads();

#pragma unroll
        for (int k4 = 0; k4 < 4; k4++) {
            int k4g = chunk * 4 + k4;
            const float* wbase = wt2 + k4g * 128 + cg * 4;
            ulonglong2 xv[4];
#pragma unroll
            for (int q = 0; q < 4; q++)
                xv[q] = *(const ulonglong2*)&xs[(rg + q * 64) * XS_STRIDE + k4 * 4];
#pragma unroll
            for (int ch = 0; ch < 2; ch++) {
                ulonglong2 wv[4];
#pragma unroll
                for (int c = 0; c < 4; c++)
                    wv[c] = *(const ulonglong2*)(wbase + (ch * 4 + c) * 16);
#pragma unroll
                for (int q = 0; q < 4; q++)
#pragma unroll
                    for (int c = 0; c < 4; c++)
                        ffma2(acc[q][ch * 4 + c], xv[q].x, wv[c].x);
#pragma unroll
                for (int q = 0; q < 4; q++)
#pragma unroll
                    for (int c = 0; c < 4; c++)
                        ffma2(acc[q][ch * 4 + c], xv[q].y, wv[c].y);
            }
        }
    }

#pragma unroll
    for (int q = 0; q < 4; q++) {
        int gr = row0 + rg + q * 64;
        if (gr < N_NODES) {
            float o[8];
#pragma unroll
            for (int c = 0; c < 8; c++) {
                float2 a = *(float2*)&acc[q][c];
                o[c] = a.x + a.y;
            }
            if (cg < 2) {
                *(float4*)(&g_ps[gr * 16 + cg * 8])     = make_float4(o[0], o[1], o[2], o[3]);
                *(float4*)(&g_ps[gr * 16 + cg * 8 + 4]) = make_float4(o[4], o[5], o[6], o[7]);
            } else {
                __half2 hh[4];
                hh[0] = __floats2half2_rn(o[0], o[1]);
                hh[1] = __floats2half2_rn(o[2], o[3]);
                hh[2] = __floats2half2_rn(o[4], o[5]);
                hh[3] = __floats2half2_rn(o[6], o[7]);
                *(uint4*)(&g_pn[gr * 16 + (cg - 2) * 8]) = *(uint4*)hh;
            }
        }
    }
}

__device__ __forceinline__ int warp_sum(int v) {
#pragma unroll
    for (int o = 16; o; o >>= 1) v += __shfl_xor_sync(0xffffffffu, v, o);
    return v;
}

// -------- single-pass exclusive scan over g_deg (decoupled lookback) --------
__global__ void __launch_bounds__(512) k_scan() {
    __shared__ int s[512];
    __shared__ int s_prev;
    int b = blockIdx.x, t = threadIdx.x;
    int i = b * 512 + t;
    int v = (i < N_NODES) ? g_deg[i] : 0;
    if (i < N_NODES) g_deg[i] = 0;        // restore invariant
    s[t] = v;
    __syncthreads();
#pragma unroll
    for (int off = 1; off < 512; off <<= 1) {
        int tv = (t >= off) ? s[t - off] : 0;
        __syncthreads();
        s[t] += tv;
        __syncthreads();
    }
    int incl = s[t];
    int blocksum = s[511];

    if (t == 0) {
        unsigned long long pkg = ((b == 0) ? (2ULL << 32) : (1ULL << 32))
                               | (unsigned int)blocksum;
        *(volatile unsigned long long*)&g_scanstate[b] = pkg;
    }

    if (t < 32) {
        int prefix = 0;
        int look = b - 1;
        while (look >= 0) {
            int idx = look - t;
            unsigned long long st = (idx >= 0)
                ? *(volatile unsigned long long*)&g_scanstate[idx]
                : (2ULL << 32);
            unsigned int flag = (unsigned int)(st >> 32);
            int val = (int)(st & 0xffffffffu);
            unsigned int nr = __ballot_sync(0xffffffffu, flag == 0u);
            unsigned int pm = __ballot_sync(0xffffffffu, flag == 2u);
            int firstP = pm ? (__ffs(pm) - 1) : 32;
            unsigned int below = (firstP < 32) ? ((1u << firstP) - 1u) : 0xffffffffu;
            if (firstP < 32 && (nr & below) == 0u) {
                int c = (t <= firstP) ? val : 0;
                prefix += warp_sum(c);
                break;
            } else if (nr == 0u) {
                prefix += warp_sum(val);
                look -= 32;
            }
        }
        if (t == 0) {
            s_prev = prefix;
            *(volatile unsigned long long*)&g_scanstate[b] =
                (2ULL << 32) | (unsigned int)(prefix + blocksum);
        }
    }
    __syncthreads();
    int base = s_prev;
    if (i < N_NODES)
        g_rowptr[i] = base + incl - v;
    if (b == NSCAN_BLOCKS - 1 && t == 511)
        g_rowptr[N_NODES] = base + incl;
}

// -------- fill: pos = rowptr[dst] + rank  (no atomics) --------
__global__ void k_fill(const int* __restrict__ src, const int* __restrict__ dst) {
    int e = blockIdx.x * blockDim.x + threadIdx.x;
    if (e * 4 < N_EDGES) {
        int4 s4 = ((const int4*)src)[e];
        int4 d4 = ((const int4*)dst)[e];
        int4 r4 = ((const int4*)g_rank)[e];
        g_eidx[__ldg(&g_rowptr[d4.x]) + r4.x] = s4.x;
        g_eidx[__ldg(&g_rowptr[d4.y]) + r4.y] = s4.y;
        g_eidx[__ldg(&g_rowptr[d4.z]) + r4.z] = s4.z;
        g_eidx[__ldg(&g_rowptr[d4.w]) + r4.w] = s4.w;
    }
}

// convert 4 halves (uint2) and accumulate into 4 fp32 accs
__device__ __forceinline__ void addh4(float* a, uint2 u) {
    float2 f0 = __half22float2(*(__half2*)&u.x);
    float2 f1 = __half22float2(*(__half2*)&u.y);
    a[0] += f0.x; a[1] += f0.y;
    a[2] += f1.x; a[3] += f1.y;
}

// -------- layer-1 aggregate + combine + relu (4 lanes/node, fp16 gather) ----
__global__ void __launch_bounds__(256) k_agg1(const float* __restrict__ b1) {
    int t = blockIdx.x * blockDim.x + threadIdx.x;
    int n = t >> 2;
    int fq = t & 3;              // features fq*4 .. fq*4+3
    if (n >= N_NODES) return;
    int beg = g_rowptr[n];
    int end = g_rowptr[n + 1];
    float acc[4] = {0, 0, 0, 0};
    float acd[4] = {0, 0, 0, 0};
    int i = beg;
    for (; i + 4 <= end; i += 4) {
        int s0 = g_eidx[i], s1 = g_eidx[i + 1], s2 = g_eidx[i + 2], s3 = g_eidx[i + 3];
        uint2 u0 = *(const uint2*)&g_pn[s0 * 16 + fq * 4];
        uint2 u1 = *(const uint2*)&g_pn[s1 * 16 + fq * 4];
        uint2 u2 = *(const uint2*)&g_pn[s2 * 16 + fq * 4];
        uint2 u3 = *(const uint2*)&g_pn[s3 * 16 + fq * 4];
        addh4(acc, u0); addh4(acd, u1); addh4(acc, u2); addh4(acd, u3);
    }
    for (; i < end; i++) {
        uint2 u = *(const uint2*)&g_pn[g_eidx[i] * 16 + fq * 4];
        addh4(acc, u);
    }
#pragma unroll
    for (int j = 0; j < 4; j++) acc[j] += acd[j];

    float inv = 1.f / fmaxf((float)(end - beg), 1.f);
    float4 self = *(const float4*)&g_ps[n * 16 + fq * 4];
    float4 bb = *(const float4*)&b1[fq * 4];
    float4 o;
    o.x = fmaxf(self.x + acc[0] * inv + bb.x, 0.f);
    o.y = fmaxf(self.y + acc[1] * inv + bb.y, 0.f);
    o.z = fmaxf(self.z + acc[2] * inv + bb.z, 0.f);
    o.w = fmaxf(self.w + acc[3] * inv + bb.w, 0.f);
    *(float4*)&g_h[n * 16 + fq * 4] = o;
    __half2 hh[2];
    hh[0] = __floats2half2_rn(o.x, o.y);
    hh[1] = __floats2half2_rn(o.z, o.w);
    *(uint2*)&g_hb[n * 16 + fq * 4] = *(uint2*)hh;
}

// -------- fused layer-2 aggregate (fp16 gather, 4 lanes/node) + projection --
__global__ void __launch_bounds__(256) k_agg2out(const float* __restrict__ wn2,
                                                 const float* __restrict__ ws2,
                                                 const float* __restrict__ b2,
                                                 float* __restrict__ out) {
    __shared__ float sw[2 * 640];     // ws2 | wn2 (k*40+c)
    __shared__ float sb[40];
    __shared__ float sh[64 * 16];     // h per node (fp32)
    __shared__ float sm[64 * 16];     // mean per node (fp32)
    int t = threadIdx.x;
    for (int i = t; i < 640; i += 256) { sw[i] = ws2[i]; sw[640 + i] = wn2[i]; }
    if (t < 40) sb[t] = b2[t];

    int n0 = blockIdx.x * 64;
    int nl = t >> 2, fq = t & 3;
    int n = n0 + nl;
    float acc[4] = {0, 0, 0, 0};
    float4 hv = make_float4(0.f, 0.f, 0.f, 0.f);
    if (n < N_NODES) {
        int beg = g_rowptr[n];
        int end = g_rowptr[n + 1];
        float acd[4] = {0, 0, 0, 0};
        int i = beg;
        for (; i + 4 <= end; i += 4) {
            int s0 = g_eidx[i], s1 = g_eidx[i + 1], s2 = g_eidx[i + 2], s3 = g_eidx[i + 3];
            uint2 u0 = *(const uint2*)&g_hb[s0 * 16 + fq * 4];
            uint2 u1 = *(const uint2*)&g_hb[s1 * 16 + fq * 4];
            uint2 u2 = *(const uint2*)&g_hb[s2 * 16 + fq * 4];
            uint2 u3 = *(const uint2*)&g_hb[s3 * 16 + fq * 4];
            addh4(acc, u0); addh4(acd, u1); addh4(acc, u2); addh4(acd, u3);
        }
        for (; i < end; i++) {
            uint2 u = *(const uint2*)&g_hb[g_eidx[i] * 16 + fq * 4];
            addh4(acc, u);
        }
        float inv = 1.f / fmaxf((float)(end - beg), 1.f);
#pragma unroll
        for (int j = 0; j < 4; j++) acc[j] = (acc[j] + acd[j]) * inv;
        hv = *(const float4*)&g_h[n * 16 + fq * 4];
    }
    *(float4*)&sh[nl * 16 + fq * 4] = hv;
    *(float4*)&sm[nl * 16 + fq * 4] = make_float4(acc[0], acc[1], acc[2], acc[3]);
    __syncthreads();

#pragma unroll
    for (int o = t; o < 64 * 40; o += 256) {
        int n2 = o / 40, c = o % 40;
        int gn = n0 + n2;
        if (gn < N_NODES) {
            float a = sb[c];
#pragma unroll
            for (int k = 0; k < 16; k++)
                a += sh[n2 * 16 + k] * sw[k * 40 + c]
                   + sm[n2 * 16 + k] * sw[640 + k * 40 + c];
            out[gn * 40 + c] = a;
        }
    }
}

extern "C" void kernel_launch(void* const* d_in, const int* in_sizes, int n_in,
                              void* d_out, int out_size) {
    const float* x   = (const float*)d_in[0];
    const int*   src = (const int*)d_in[1];
    const int*   dst = (const int*)d_in[2];
    const float* wn1 = (const float*)d_in[3];
    const float* ws1 = (const float*)d_in[4];
    const float* b1  = (const float*)d_in[5];
    const float* wn2 = (const float*)d_in[6];
    const float* ws2 = (const float*)d_in[7];
    const float* b2  = (const float*)d_in[8];
    float* out = (float*)d_out;

    k_gemm_count<<<TOTAL_BLOCKS, 256>>>(x, wn1, ws1, dst);                // idx 0
    k_scan<<<NSCAN_BLOCKS, 512>>>();                                      // idx 1
    k_fill<<<EDGE_BLOCKS, 256>>>(src, dst);                               // idx 2
    k_agg1<<<(N_NODES * 4 + 255) / 256, 256>>>(b1);                       // idx 3 -> profiled
    k_agg2out<<<(N_NODES + 63) / 64, 256>>>(wn2, ws2, b2, out);           // idx 4
}

// round 17
// speedup vs baseline: 1.1039x; 1.1039x over previous
#include <cuda_runtime.h>
#include <cuda_bf16.h>
#include <cuda_fp16.h>

#define N_NODES 100000
#define N_EDGES 1600000
#define NFEAT   128
#define NHID    16
#define NCLS    40
#define NSCAN_BLOCKS 196
#define GEMM_BLOCKS ((N_NODES + 255) / 256)          // 391
#define EDGE_BLOCKS ((N_EDGES / 4 + 255) / 256)      // 1563
#define TOTAL_BLOCKS (GEMM_BLOCKS + EDGE_BLOCKS)     // 1954

// -------- scratch (device globals; zero-initialized at module load) --------
__device__ float  g_ps[N_NODES * 16];   // x @ w_self1  (fp32)
__device__ __half g_pn[N_NODES * 16];   // x @ w_neigh1 (fp16, gathered per edge)
__device__ float  g_h [N_NODES * 16];   // layer-1 out fp32
__device__ __half g_hb[N_NODES * 16];   // layer-1 out fp16 (gathered per edge)
__device__ int    g_deg[N_NODES];       // INVARIANT: zero at entry/exit
__device__ int    g_rowptr[N_NODES + 1];
__device__ int    g_rank[N_EDGES];
__device__ int    g_eidx[N_EDGES];
__device__ unsigned long long g_scanstate[NSCAN_BLOCKS];

// ===================== fused FFMA2 GEMM1 + degree count (R14 config) =========
#define XS_STRIDE 36

__device__ __forceinline__ void ffma2(unsigned long long& acc,
                                      unsigned long long a,
                                      unsigned long long b) {
    asm("fma.rn.f32x2 %0, %1, %2, %0;" : "+l"(acc) : "l"(a), "l"(b));
}

__global__ void __launch_bounds__(256, 2) k_gemm_count(const float* __restrict__ x,
                                                       const float* __restrict__ wn1,
                                                       const float* __restrict__ ws1,
                                                       const int* __restrict__ dst) {
    __shared__ __align__(16) float xs[256 * XS_STRIDE];   // 36 KB
    __shared__ __align__(16) float wt2[4096];             // 16 KB
    int tid = threadIdx.x;

    if (blockIdx.x >= GEMM_BLOCKS) {
        // ---- count branch ----
        int cb = blockIdx.x - GEMM_BLOCKS;
        if (cb == 0 && tid < NSCAN_BLOCKS)
            *(volatile unsigned long long*)&g_scanstate[tid] = 0ULL;
        int e = cb * 256 + tid;
        if (e * 4 < N_EDGES) {
            int4 d = ((const int4*)dst)[e];
            int4 r;
            r.x = atomicAdd(&g_deg[d.x], 1);
            r.y = atomicAdd(&g_deg[d.y], 1);
            r.z = atomicAdd(&g_deg[d.z], 1);
            r.w = atomicAdd(&g_deg[d.w], 1);
            ((int4*)g_rank)[e] = r;
        }
        return;
    }

    // ---- gemm branch: 256 rows x 32 cols, f32x2 FFMA ----
    int row0 = blockIdx.x * 256;

    // pack weights: wt2[k4g*128 + c*16 + cg*4 + j] = W[k4g*4+j][cg*8+c]
    for (int i = tid; i < 4096; i += 256) {
        int j   = i & 3;
        int cg  = (i >> 2) & 3;
        int c   = (i >> 4) & 7;
        int k4g = i >> 7;
        int col = cg * 8 + c;
        int k   = k4g * 4 + j;
        wt2[i] = (col < 16) ? ws1[k * 16 + col] : wn1[k * 16 + (col - 16)];
    }

    int cg = tid & 3;        // col group (0..3), 8 cols each
    int rg = tid >> 2;       // row group (0..63), rows rg + q*64

    unsigned long long acc[4][8];
#pragma unroll
    for (int q = 0; q < 4; q++)
#pragma unroll
        for (int c = 0; c < 8; c++) acc[q][c] = 0ULL;

#pragma unroll
    for (int chunk = 0; chunk < 4; chunk++) {
        __syncthreads();
        // stage 256 rows x 32 floats, coalesced
#pragma unroll
        for (int l = 0; l < 8; l++) {
            int f = l * 256 + tid;
            int row = f >> 3, slot = f & 7;
            int gr = row0 + row;
            if (gr >= N_NODES) gr = N_NODES - 1;   // clamp; stores guarded
            *(float4*)&xs[row * XS_STRIDE + slot * 4] =
                *(const float4*)&x[gr * 128 + chunk * 32 + slot * 4];
        }
        __syncthreads();

#pragma unroll
        for (int k4 = 0; k4 < 8; k4++) {
            int k4g = chunk * 8 + k4;
            const float* wbase = wt2 + k4g * 128 + cg * 4;
            ulonglong2 xv[4];
#pragma unroll
            for (int q = 0; q < 4; q++)
                xv[q] = *(const ulonglong2*)&xs[(rg + q * 64) * XS_STRIDE + k4 * 4];
#pragma unroll
            for (int ch = 0; ch < 2; ch++) {
                ulonglong2 wv[4];
#pragma unroll
                for (int c = 0; c < 4; c++)
                    wv[c] = *(const ulonglong2*)(wbase + (ch * 4 + c) * 16);
#pragma unroll
                for (int q = 0; q < 4; q++)
#pragma unroll
                    for (int c = 0; c < 4; c++)
                        ffma2(acc[q][ch * 4 + c], xv[q].x, wv[c].x);
#pragma unroll
                for (int q = 0; q < 4; q++)
#pragma unroll
                    for (int c = 0; c < 4; c++)
                        ffma2(acc[q][ch * 4 + c], xv[q].y, wv[c].y);
            }
        }
    }

#pragma unroll
    for (int q = 0; q < 4; q++) {
        int gr = row0 + rg + q * 64;
        if (gr < N_NODES) {
            float o[8];
#pragma unroll
            for (int c = 0; c < 8; c++) {
                float2 a = *(float2*)&acc[q][c];
                o[c] = a.x + a.y;
            }
            if (cg < 2) {
                *(float4*)(&g_ps[gr * 16 + cg * 8])     = make_float4(o[0], o[1], o[2], o[3]);
                *(float4*)(&g_ps[gr * 16 + cg * 8 + 4]) = make_float4(o[4], o[5], o[6], o[7]);
            } else {
                __half2 hh[4];
                hh[0] = __floats2half2_rn(o[0], o[1]);
                hh[1] = __floats2half2_rn(o[2], o[3]);
                hh[2] = __floats2half2_rn(o[4], o[5]);
                hh[3] = __floats2half2_rn(o[6], o[7]);
                *(uint4*)(&g_pn[gr * 16 + (cg - 2) * 8]) = *(uint4*)hh;
            }
        }
    }
}

__device__ __forceinline__ int warp_sum(int v) {
#pragma unroll
    for (int o = 16; o; o >>= 1) v += __shfl_xor_sync(0xffffffffu, v, o);
    return v;
}

// -------- single-pass exclusive scan over g_deg (decoupled lookback) --------
__global__ void __launch_bounds__(512) k_scan() {
    __shared__ int s[512];
    __shared__ int s_prev;
    int b = blockIdx.x, t = threadIdx.x;
    int i = b * 512 + t;
    int v = (i < N_NODES) ? g_deg[i] : 0;
    if (i < N_NODES) g_deg[i] = 0;        // restore invariant
    s[t] = v;
    __syncthreads();
#pragma unroll
    for (int off = 1; off < 512; off <<= 1) {
        int tv = (t >= off) ? s[t - off] : 0;
        __syncthreads();
        s[t] += tv;
        __syncthreads();
    }
    int incl = s[t];
    int blocksum = s[511];

    if (t == 0) {
        unsigned long long pkg = ((b == 0) ? (2ULL << 32) : (1ULL << 32))
                               | (unsigned int)blocksum;
        *(volatile unsigned long long*)&g_scanstate[b] = pkg;
    }

    if (t < 32) {
        int prefix = 0;
        int look = b - 1;
        while (look >= 0) {
            int idx = look - t;
            unsigned long long st = (idx >= 0)
                ? *(volatile unsigned long long*)&g_scanstate[idx]
                : (2ULL << 32);
            unsigned int flag = (unsigned int)(st >> 32);
            int val = (int)(st & 0xffffffffu);
            unsigned int nr = __ballot_sync(0xffffffffu, flag == 0u);
            unsigned int pm = __ballot_sync(0xffffffffu, flag == 2u);
            int firstP = pm ? (__ffs(pm) - 1) : 32;
            unsigned int below = (firstP < 32) ? ((1u << firstP) - 1u) : 0xffffffffu;
            if (firstP < 32 && (nr & below) == 0u) {
                int c = (t <= firstP) ? val : 0;
                prefix += warp_sum(c);
                break;
            } else if (nr == 0u) {
                prefix += warp_sum(val);
                look -= 32;
            }
        }
        if (t == 0) {
            s_prev = prefix;
            *(volatile unsigned long long*)&g_scanstate[b] =
                (2ULL << 32) | (unsigned int)(prefix + blocksum);
        }
    }
    __syncthreads();
    int base = s_prev;
    if (i < N_NODES)
        g_rowptr[i] = base + incl - v;
    if (b == NSCAN_BLOCKS - 1 && t == 511)
        g_rowptr[N_NODES] = base + incl;
}

// -------- fill: pos = rowptr[dst] + rank  (no atomics) --------
__global__ void k_fill(const int* __restrict__ src, const int* __restrict__ dst) {
    int e = blockIdx.x * blockDim.x + threadIdx.x;
    if (e * 4 < N_EDGES) {
        int4 s4 = ((const int4*)src)[e];
        int4 d4 = ((const int4*)dst)[e];
        int4 r4 = ((const int4*)g_rank)[e];
        g_eidx[__ldg(&g_rowptr[d4.x]) + r4.x] = s4.x;
        g_eidx[__ldg(&g_rowptr[d4.y]) + r4.y] = s4.y;
        g_eidx[__ldg(&g_rowptr[d4.z]) + r4.z] = s4.z;
        g_eidx[__ldg(&g_rowptr[d4.w]) + r4.w] = s4.w;
    }
}

// convert 4 halves (uint2) and accumulate into 4 fp32 accs
__device__ __forceinline__ void addh4(float* a, uint2 u) {
    float2 f0 = __half22float2(*(__half2*)&u.x);
    float2 f1 = __half22float2(*(__half2*)&u.y);
    a[0] += f0.x; a[1] += f0.y;
    a[2] += f1.x; a[3] += f1.y;
}

// -------- layer-1 aggregate + combine + relu (4 lanes/node, fp16 gather) ----
__global__ void __launch_bounds__(256) k_agg1(const float* __restrict__ b1) {
    int t = blockIdx.x * blockDim.x + threadIdx.x;
    int n = t >> 2;
    int fq = t & 3;              // features fq*4 .. fq*4+3
    if (n >= N_NODES) return;
    int beg = g_rowptr[n];
    int end = g_rowptr[n + 1];
    float acc[4] = {0, 0, 0, 0};
    float acd[4] = {0, 0, 0, 0};
    int i = beg;
    for (; i + 4 <= end; i += 4) {
        int s0 = g_eidx[i], s1 = g_eidx[i + 1], s2 = g_eidx[i + 2], s3 = g_eidx[i + 3];
        uint2 u0 = *(const uint2*)&g_pn[s0 * 16 + fq * 4];
        uint2 u1 = *(const uint2*)&g_pn[s1 * 16 + fq * 4];
        uint2 u2 = *(const uint2*)&g_pn[s2 * 16 + fq * 4];
        uint2 u3 = *(const uint2*)&g_pn[s3 * 16 + fq * 4];
        addh4(acc, u0); addh4(acd, u1); addh4(acc, u2); addh4(acd, u3);
    }
    for (; i < end; i++) {
        uint2 u = *(const uint2*)&g_pn[g_eidx[i] * 16 + fq * 4];
        addh4(acc, u);
    }
#pragma unroll
    for (int j = 0; j < 4; j++) acc[j] += acd[j];

    float inv = 1.f / fmaxf((float)(end - beg), 1.f);
    float4 self = *(const float4*)&g_ps[n * 16 + fq * 4];
    float4 bb = *(const float4*)&b1[fq * 4];
    float4 o;
    o.x = fmaxf(self.x + acc[0] * inv + bb.x, 0.f);
    o.y = fmaxf(self.y + acc[1] * inv + bb.y, 0.f);
    o.z = fmaxf(self.z + acc[2] * inv + bb.z, 0.f);
    o.w = fmaxf(self.w + acc[3] * inv + bb.w, 0.f);
    *(float4*)&g_h[n * 16 + fq * 4] = o;
    __half2 hh[2];
    hh[0] = __floats2half2_rn(o.x, o.y);
    hh[1] = __floats2half2_rn(o.z, o.w);
    *(uint2*)&g_hb[n * 16 + fq * 4] = *(uint2*)hh;
}

// -------- fused layer-2 aggregate (fp16 gather) + projection -----------------
// Gather phase: 4 lanes/node (identical to R14). Projection phase: each thread
// owns one node (n2 = t>>2) and 10 output columns; node's h/m cached in regs.
__global__ void __launch_bounds__(256) k_agg2out(const float* __restrict__ wn2,
                                                 const float* __restrict__ ws2,
                                                 const float* __restrict__ b2,
                                                 float* __restrict__ out) {
    __shared__ float sw[2 * 640];     // ws2 | wn2 (k*40+c)
    __shared__ float sb[40];
    __shared__ float sh[64 * 16];     // h per node (fp32)
    __shared__ float sm[64 * 16];     // mean per node (fp32)
    int t = threadIdx.x;
    for (int i = t; i < 640; i += 256) { sw[i] = ws2[i]; sw[640 + i] = wn2[i]; }
    if (t < 40) sb[t] = b2[t];

    int n0 = blockIdx.x * 64;
    int nl = t >> 2, fq = t & 3;
    int n = n0 + nl;
    float acc[4] = {0, 0, 0, 0};
    float4 hv = make_float4(0.f, 0.f, 0.f, 0.f);
    if (n < N_NODES) {
        int beg = g_rowptr[n];
        int end = g_rowptr[n + 1];
        float acd[4] = {0, 0, 0, 0};
        int i = beg;
        for (; i + 4 <= end; i += 4) {
            int s0 = g_eidx[i], s1 = g_eidx[i + 1], s2 = g_eidx[i + 2], s3 = g_eidx[i + 3];
            uint2 u0 = *(const uint2*)&g_hb[s0 * 16 + fq * 4];
            uint2 u1 = *(const uint2*)&g_hb[s1 * 16 + fq * 4];
            uint2 u2 = *(const uint2*)&g_hb[s2 * 16 + fq * 4];
            uint2 u3 = *(const uint2*)&g_hb[s3 * 16 + fq * 4];
            addh4(acc, u0); addh4(acd, u1); addh4(acc, u2); addh4(acd, u3);
        }
        for (; i < end; i++) {
            uint2 u = *(const uint2*)&g_hb[g_eidx[i] * 16 + fq * 4];
            addh4(acc, u);
        }
        float inv = 1.f / fmaxf((float)(end - beg), 1.f);
#pragma unroll
        for (int j = 0; j < 4; j++) acc[j] = (acc[j] + acd[j]) * inv;
        hv = *(const float4*)&g_h[n * 16 + fq * 4];
    }
    *(float4*)&sh[nl * 16 + fq * 4] = hv;
    *(float4*)&sm[nl * 16 + fq * 4] = make_float4(acc[0], acc[1], acc[2], acc[3]);
    __syncthreads();

    // projection: thread owns node n2 = t>>2 and 10 cols c0 = (t&3)*10
    {
        int n2 = t >> 2;
        int c0 = (t & 3) * 10;
        int gn = n0 + n2;
        float hk[16], mk[16];
#pragma unroll
        for (int k4 = 0; k4 < 4; k4++) {
            *(float4*)&hk[k4 * 4] = *(const float4*)&sh[n2 * 16 + k4 * 4];
            *(float4*)&mk[k4 * 4] = *(const float4*)&sm[n2 * 16 + k4 * 4];
        }
        if (gn < N_NODES) {
#pragma unroll
            for (int cc = 0; cc < 10; cc++) {
                int c = c0 + cc;
                float a = sb[c];
#pragma unroll
                for (int k = 0; k < 16; k++)
                    a += hk[k] * sw[k * 40 + c] + mk[k] * sw[640 + k * 40 + c];
                out[gn * 40 + c] = a;
            }
        }
    }
}

extern "C" void kernel_launch(void* const* d_in, const int* in_sizes, int n_in,
                              void* d_out, int out_size) {
    const float* x   = (const float*)d_in[0];
    const int*   src = (const int*)d_in[1];
    const int*   dst = (const int*)d_in[2];
    const float* wn1 = (const float*)d_in[3];
    const float* ws1 = (const float*)d_in[4];
    const float* b1  = (const float*)d_in[5];
    const float* wn2 = (const float*)d_in[6];
    const float* ws2 = (const float*)d_in[7];
    const float* b2  = (const float*)d_in[8];
    float* out = (float*)d_out;

    k_gemm_count<<<TOTAL_BLOCKS, 256>>>(x, wn1, ws1, dst);                // idx 0
    k_scan<<<NSCAN_BLOCKS, 512>>>();                                      // idx 1
    k_fill<<<EDGE_BLOCKS, 256>>>(src, dst);                               // idx 2
    k_agg1<<<(N_NODES * 4 + 255) / 256, 256>>>(b1);                       // idx 3 -> profiled
    k_agg2out<<<(N_NODES + 63) / 64, 256>>>(wn2, ws2, b2, out);           // idx 4
}